// round 2
// baseline (speedup 1.0000x reference)
#include <cuda_runtime.h>

// Problem constants (fixed by reference setup_inputs)
#define B   32
#define C   32      // C_in == C_out == 32
#define H   256
#define W   256
#define TSX 32      // spatial tile width  (x)
#define TSY 8       // spatial tile height (y)

#define IN_W     34             // TSX + 2 halo
#define IN_H     10             // TSY + 2 halo
#define IN_STR   35             // padded row stride (conflict-free banks)
#define IN_PER_C (IN_H * IN_STR)            // 350 floats per channel
#define SMEM_IN  (C * IN_PER_C)             // 11200 floats
#define SMEM_W   (C * C * 9)                // 9216 floats
#define SMEM_FLOATS (SMEM_IN + SMEM_W)      // 20416 -> 81664 bytes

__global__ void __launch_bounds__(256, 2)
batch_conv3x3_kernel(const float* __restrict__ x,
                     const float* __restrict__ w,
                     const float* __restrict__ bias,
                     float* __restrict__ out)
{
    extern __shared__ float smem[];
    float* in_s = smem;             // [C][IN_H][IN_STR]
    float* w_s  = smem + SMEM_IN;   // [ci][oc][9]

    const int tid   = threadIdx.x;
    const int tileX = blockIdx.x;   // 0..7
    const int tileY = blockIdx.y;   // 0..31
    const int b     = blockIdx.z;   // 0..31

    // ---- load weights for this batch: gmem [oc][ci][3][3] -> smem [ci][oc][9]
    const float* wg = w + (size_t)b * (C * C * 9);
    for (int idx = tid; idx < C * C * 9; idx += 256) {
        int oc  = idx / (C * 9);
        int rem = idx - oc * (C * 9);
        int ci  = rem / 9;
        int tap = rem - ci * 9;
        w_s[(ci * C + oc) * 9 + tap] = wg[idx];
    }

    // ---- load input tile (with zero-padded halo) for all 32 channels
    const int y0 = tileY * TSY - 1;
    const int x0 = tileX * TSX - 1;
    const float* xb = x + (size_t)b * C * H * W;
    for (int idx = tid; idx < C * IN_H * IN_W; idx += 256) {
        int ci  = idx / (IN_H * IN_W);
        int rem = idx - ci * (IN_H * IN_W);
        int r   = rem / IN_W;
        int c   = rem - r * IN_W;
        int gy  = y0 + r;
        int gx  = x0 + c;
        float v = 0.0f;
        if ((unsigned)gy < (unsigned)H && (unsigned)gx < (unsigned)W)
            v = xb[ci * (H * W) + gy * W + gx];
        in_s[ci * IN_PER_C + r * IN_STR + c] = v;
    }
    __syncthreads();

    // ---- thread mapping: 4 oc-groups x 64 segments (8y x 8x, 4 px each)
    const int ocg   = tid >> 6;         // 0..3  -> oc base = ocg*8
    const int seg   = tid & 63;
    const int seg_y = seg >> 3;         // 0..7
    const int seg_x = seg & 7;          // 0..7  -> x base = seg_x*4

    float acc[8][4];
    const float* bb = bias + b * C + ocg * 8;
#pragma unroll
    for (int o = 0; o < 8; ++o) {
        float bv = bb[o];
#pragma unroll
        for (int p = 0; p < 4; ++p) acc[o][p] = bv;
    }

    // ---- main loop over input channels
    for (int ci = 0; ci < C; ++ci) {
        const float* ip = &in_s[ci * IN_PER_C + seg_y * IN_STR + seg_x * 4];
        float iv[3][6];
#pragma unroll
        for (int dy = 0; dy < 3; ++dy)
#pragma unroll
            for (int xx = 0; xx < 6; ++xx)
                iv[dy][xx] = ip[dy * IN_STR + xx];

        const float* wp = &w_s[(ci * C + ocg * 8) * 9];
#pragma unroll
        for (int o = 0; o < 8; ++o) {
#pragma unroll
            for (int dy = 0; dy < 3; ++dy) {
#pragma unroll
                for (int dx = 0; dx < 3; ++dx) {
                    float wv = wp[o * 9 + dy * 3 + dx];
#pragma unroll
                    for (int p = 0; p < 4; ++p)
                        acc[o][p] = fmaf(iv[dy][p + dx], wv, acc[o][p]);
                }
            }
        }
    }

    // ---- write output: 8 oc x float4
    const int gy  = tileY * TSY + seg_y;
    const int gx0 = tileX * TSX + seg_x * 4;
#pragma unroll
    for (int o = 0; o < 8; ++o) {
        int oc = ocg * 8 + o;
        float4 v = make_float4(acc[o][0], acc[o][1], acc[o][2], acc[o][3]);
        *reinterpret_cast<float4*>(
            out + (((size_t)b * C + oc) * H + gy) * W + gx0) = v;
    }
}

extern "C" void kernel_launch(void* const* d_in, const int* in_sizes, int n_in,
                              void* d_out, int out_size)
{
    const float* x    = (const float*)d_in[0];
    const float* w    = (const float*)d_in[1];
    const float* bias = (const float*)d_in[2];
    float* out        = (float*)d_out;

    const int smem_bytes = SMEM_FLOATS * sizeof(float);
    cudaFuncSetAttribute(batch_conv3x3_kernel,
                         cudaFuncAttributeMaxDynamicSharedMemorySize,
                         smem_bytes);

    dim3 grid(W / TSX, H / TSY, B);   // (8, 32, 32)
    dim3 block(256);
    batch_conv3x3_kernel<<<grid, block, smem_bytes>>>(x, w, bias, out);
}

// round 4
// speedup vs baseline: 1.5158x; 1.5158x over previous
#include <cuda_runtime.h>
#include <cuda_bf16.h>
#include <cstdint>

// ============================================================================
// BatchConv2D 3x3 via legacy tensor-core mma.sync (bf16x3 fp32 emulation).
// Per CTA: one (batch, row y, half-row of 128 px), all 32 oc.
// GEMM: M=128 (px) x N=32 (oc) x K=288 (9 taps x 32 ci), 3 split passes.
// ============================================================================

#define BATCH 32
#define CH    32
#define HH    256
#define WW    256
#define HW    (HH * WW)

// SMEM word strides chosen for conflict-free LDS in the mma loop:
//   input plane row stride 136 words:  bank = (136*j + px) % 32 = (8j + px)%32
//     lanes access j = tg (0..3 offset), px = g (0..7) -> 8*tg + g all distinct.
//   weight oc stride 148 words: bank = (148*g + tg) % 32 = (20g + tg)%32,
//     g in 0..7, tg in 0..3 -> all 32 distinct.
#define HP_STR  136                 // words per (dy,j) row, 130 used
#define W_STR   148                 // words per oc, 144 used

#define SMEM_BIAS 0                               // 32 floats = 128 B
#define SMEM_WHI  128                             // 32*148*4 = 18944 B
#define SMEM_WLO  (SMEM_WHI + CH * W_STR * 4)     // 19072
#define SMEM_HP   (SMEM_WLO + CH * W_STR * 4)     // 38016: [3][16][136] u32
#define SMEM_LP   (SMEM_HP + 3 * 16 * HP_STR * 4) // 64128
#define SMEM_TOTAL (SMEM_LP + 3 * 16 * HP_STR * 4) // 90240 B

__device__ __forceinline__ void mma_bf16(float* d, const uint32_t* a,
                                         uint32_t b0, uint32_t b1) {
    asm volatile(
        "mma.sync.aligned.m16n8k16.row.col.f32.bf16.bf16.f32 "
        "{%0,%1,%2,%3}, {%4,%5,%6,%7}, {%8,%9}, {%0,%1,%2,%3};\n"
        : "+f"(d[0]), "+f"(d[1]), "+f"(d[2]), "+f"(d[3])
        : "r"(a[0]), "r"(a[1]), "r"(a[2]), "r"(a[3]), "r"(b0), "r"(b1));
}

__device__ __forceinline__ uint32_t pack_hi(float v0, float v1,
                                            float& r0, float& r1) {
    __nv_bfloat16 h0 = __float2bfloat16(v0);
    __nv_bfloat16 h1 = __float2bfloat16(v1);
    r0 = v0 - __bfloat162float(h0);
    r1 = v1 - __bfloat162float(h1);
    return ((uint32_t)__bfloat16_as_ushort(h1) << 16) | __bfloat16_as_ushort(h0);
}

__device__ __forceinline__ uint32_t pack_lo(float r0, float r1) {
    __nv_bfloat16 l0 = __float2bfloat16(r0);
    __nv_bfloat16 l1 = __float2bfloat16(r1);
    return ((uint32_t)__bfloat16_as_ushort(l1) << 16) | __bfloat16_as_ushort(l0);
}

__global__ void __launch_bounds__(128, 2)
batch_conv3x3_mma_kernel(const float* __restrict__ x,
                         const float* __restrict__ w,
                         const float* __restrict__ bias,
                         float* __restrict__ out)
{
    extern __shared__ char smem[];
    float*    bias_s = reinterpret_cast<float*>(smem + SMEM_BIAS);
    uint32_t* whi    = reinterpret_cast<uint32_t*>(smem + SMEM_WHI);
    uint32_t* wlo    = reinterpret_cast<uint32_t*>(smem + SMEM_WLO);
    uint32_t* hp     = reinterpret_cast<uint32_t*>(smem + SMEM_HP);
    uint32_t* lp     = reinterpret_cast<uint32_t*>(smem + SMEM_LP);

    const int tid  = threadIdx.x;       // 0..127
    const int lane = tid & 31;
    const int wid  = tid >> 5;          // 0..3
    const int xh   = blockIdx.x;        // 0..1
    const int y    = blockIdx.y;        // 0..255
    const int b    = blockIdx.z;        // 0..31
    const int x0   = xh * 128;

    if (tid < CH) bias_s[tid] = bias[b * CH + tid];

    // ---- weights -> SMEM bf16 hi/lo, layout whi[oc*W_STR + tap*16 + pr],
    //      word = (ci=2pr+1 << 16) | (ci=2pr)
    const float* wg = w + (size_t)b * (CH * CH * 9);
    for (int idx = tid; idx < CH * 9 * 16; idx += 128) {
        const int oc  = idx / 144;
        const int rem = idx - oc * 144;
        const int tap = rem >> 4;
        const int pr  = rem & 15;
        const float v0 = wg[(oc * CH + 2 * pr) * 9 + tap];
        const float v1 = wg[(oc * CH + 2 * pr + 1) * 9 + tap];
        float r0, r1;
        whi[oc * W_STR + rem] = pack_hi(v0, v1, r0, r1);
        wlo[oc * W_STR + rem] = pack_lo(r0, r1);
    }

    // ---- input tile -> SMEM bf16 hi/lo ci-pair planes.
    //      hp[(dy*16+j)*HP_STR + i] packs ci {2j, 2j+1} at gx = x0-1+i.
    const float* xb = x + (size_t)b * CH * HW;
    for (int dy = 0; dy < 3; ++dy) {
        const int gy = y - 1 + dy;
        const bool yok = (unsigned)gy < (unsigned)HH;
        for (int i = tid; i < 130; i += 128) {
            const int gx = x0 - 1 + i;
            const bool ok = yok && ((unsigned)gx < (unsigned)WW);
            const float* px = xb + (size_t)(yok ? gy : 0) * WW + (ok ? gx : 0);
#pragma unroll
            for (int j = 0; j < 16; ++j) {
                const float v0 = ok ? px[(2 * j) * HW] : 0.0f;
                const float v1 = ok ? px[(2 * j + 1) * HW] : 0.0f;
                float r0, r1;
                hp[(dy * 16 + j) * HP_STR + i] = pack_hi(v0, v1, r0, r1);
                lp[(dy * 16 + j) * HP_STR + i] = pack_lo(r0, r1);
            }
        }
    }
    __syncthreads();

    // ---- mma mainloop: warp computes px [p0, p0+32) x all 32 oc
    const int g  = lane >> 2;          // group id 0..7
    const int tg = lane & 3;           // thread-in-group 0..3
    const int p0 = wid * 32;

    float acc[2][4][4];
#pragma unroll
    for (int nb = 0; nb < 4; ++nb) {
        const float b0v = bias_s[nb * 8 + tg * 2];
        const float b1v = bias_s[nb * 8 + tg * 2 + 1];
#pragma unroll
        for (int t = 0; t < 2; ++t) {
            acc[t][nb][0] = b0v; acc[t][nb][1] = b1v;
            acc[t][nb][2] = b0v; acc[t][nb][3] = b1v;
        }
    }

#pragma unroll
    for (int tap = 0; tap < 9; ++tap) {
        const int dy = tap / 3, dx = tap % 3;
#pragma unroll
        for (int half = 0; half < 2; ++half) {
            // A fragments: rows = pixels, cols = ci [half*16, +16)
            const int rj  = (dy * 16 + half * 8 + tg) * HP_STR;  // pair j = half*8+tg
            const int rj4 = rj + 4 * HP_STR;                     // j+4 (cols +8)
            uint32_t ah[2][4], al[2][4];
#pragma unroll
            for (int t = 0; t < 2; ++t) {
                const int pb = p0 + t * 16 + g + dx;
                ah[t][0] = hp[rj  + pb];     ah[t][1] = hp[rj  + pb + 8];
                ah[t][2] = hp[rj4 + pb];     ah[t][3] = hp[rj4 + pb + 8];
                al[t][0] = lp[rj  + pb];     al[t][1] = lp[rj  + pb + 8];
                al[t][2] = lp[rj4 + pb];     al[t][3] = lp[rj4 + pb + 8];
            }
            const int wb = tap * 16 + half * 8 + tg;
#pragma unroll
            for (int nb = 0; nb < 4; ++nb) {
                const int ocr = (nb * 8 + g) * W_STR + wb;
                const uint32_t bh0 = whi[ocr], bh1 = whi[ocr + 4];
                const uint32_t bl0 = wlo[ocr], bl1 = wlo[ocr + 4];
                mma_bf16(acc[0][nb], ah[0], bh0, bh1);
                mma_bf16(acc[1][nb], ah[1], bh0, bh1);
                mma_bf16(acc[0][nb], al[0], bh0, bh1);
                mma_bf16(acc[1][nb], al[1], bh0, bh1);
                mma_bf16(acc[0][nb], ah[0], bl0, bl1);
                mma_bf16(acc[1][nb], ah[1], bl0, bl1);
            }
        }
    }

    // ---- store: D row = pixel, col = oc
    float* ob = out + (size_t)b * CH * HW + (size_t)y * WW + x0;
#pragma unroll
    for (int t = 0; t < 2; ++t) {
        const int p = p0 + t * 16 + g;
#pragma unroll
        for (int nb = 0; nb < 4; ++nb) {
            const int oc0 = nb * 8 + tg * 2;
            ob[(size_t)oc0 * HW + p]           = acc[t][nb][0];
            ob[(size_t)(oc0 + 1) * HW + p]     = acc[t][nb][1];
            ob[(size_t)oc0 * HW + p + 8]       = acc[t][nb][2];
            ob[(size_t)(oc0 + 1) * HW + p + 8] = acc[t][nb][3];
        }
    }
}

extern "C" void kernel_launch(void* const* d_in, const int* in_sizes, int n_in,
                              void* d_out, int out_size)
{
    const float* x    = (const float*)d_in[0];
    const float* w    = (const float*)d_in[1];
    const float* bias = (const float*)d_in[2];
    float* out        = (float*)d_out;

    cudaFuncSetAttribute(batch_conv3x3_mma_kernel,
                         cudaFuncAttributeMaxDynamicSharedMemorySize,
                         SMEM_TOTAL);

    dim3 grid(2, HH, BATCH);     // 16384 CTAs
    batch_conv3x3_mma_kernel<<<grid, 128, SMEM_TOTAL>>>(x, w, bias, out);
}

// round 5
// speedup vs baseline: 2.1689x; 1.4308x over previous
#include <cuda_runtime.h>
#include <cuda_bf16.h>
#include <cstdint>

// ============================================================================
// BatchConv2D 3x3 via mma.sync bf16x3 (fp32 emulated), row-persistent CTAs.
// CTA = 256 threads (8 warps): one (batch, x-half of 128 px, 8 y rows), 32 oc.
// Per 2-row step: warps 0-3 -> row y, warps 4-7 -> row y+1; each warp does a
// 32px x 32oc tile. Input rows live in a 4-slot ring (hi/lo bf16 pair-packed);
// weights staged once per CTA.
// ============================================================================

#define BATCH 32
#define CH    32
#define HH    256
#define WW    256
#define HW    (HH * WW)
#define ROWS_PER_CTA 8

// Conflict-free SMEM strides (see bank proofs in R4):
//   input plane row stride 136 words: bank(136*tg + g) = 8tg+g, all distinct
//   weight oc stride 148 words:       bank(148*g + tg) = 20g+tg, all distinct
#define HP_STR  136                 // words per (slot,j) row, 130 used
#define W_STR   148                 // words per oc, 144 used
#define SLOT_W  (16 * HP_STR)       // 2176 words per ring slot (== 0 mod 32)

#define SMEM_BIAS 0                                   // 128 B
#define SMEM_WHI  128                                 // 18944 B
#define SMEM_WLO  (SMEM_WHI + CH * W_STR * 4)         // 19072
#define SMEM_HP   (SMEM_WLO + CH * W_STR * 4)         // 38016: 4 slots
#define SMEM_LP   (SMEM_HP + 4 * SLOT_W * 4)          // 72832
#define SMEM_TOTAL (SMEM_LP + 4 * SLOT_W * 4)         // 107648 B

__device__ __forceinline__ void mma_bf16(float* d, const uint32_t* a,
                                         uint32_t b0, uint32_t b1) {
    asm volatile(
        "mma.sync.aligned.m16n8k16.row.col.f32.bf16.bf16.f32 "
        "{%0,%1,%2,%3}, {%4,%5,%6,%7}, {%8,%9}, {%0,%1,%2,%3};\n"
        : "+f"(d[0]), "+f"(d[1]), "+f"(d[2]), "+f"(d[3])
        : "r"(a[0]), "r"(a[1]), "r"(a[2]), "r"(a[3]), "r"(b0), "r"(b1));
}

__device__ __forceinline__ uint32_t pack_hi(float v0, float v1,
                                            float& r0, float& r1) {
    __nv_bfloat16 h0 = __float2bfloat16(v0);
    __nv_bfloat16 h1 = __float2bfloat16(v1);
    r0 = v0 - __bfloat162float(h0);
    r1 = v1 - __bfloat162float(h1);
    return ((uint32_t)__bfloat16_as_ushort(h1) << 16) | __bfloat16_as_ushort(h0);
}

__device__ __forceinline__ uint32_t pack_lo(float r0, float r1) {
    __nv_bfloat16 l0 = __float2bfloat16(r0);
    __nv_bfloat16 l1 = __float2bfloat16(r1);
    return ((uint32_t)__bfloat16_as_ushort(l1) << 16) | __bfloat16_as_ushort(l0);
}

// Stage one global input row gy into ring slot (gy+4)&3. Zero-fills OOB.
__device__ __forceinline__ void stage_row(uint32_t* hp, uint32_t* lp,
                                          const float* __restrict__ xb,
                                          int gy, int x0, int tid) {
    const int slot = (gy + 4) & 3;
    uint32_t* hs = hp + slot * SLOT_W;
    uint32_t* ls = lp + slot * SLOT_W;
    const bool yok = (unsigned)gy < (unsigned)HH;
    const float* rowp = xb + (size_t)(yok ? gy : 0) * WW;
    for (int idx = tid; idx < 16 * 130; idx += 256) {
        const int j = idx / 130;
        const int i = idx - j * 130;
        const int gx = x0 - 1 + i;
        const bool ok = yok && ((unsigned)gx < (unsigned)WW);
        const float* px = rowp + (ok ? gx : 0);
        const float v0 = ok ? px[(2 * j) * HW] : 0.0f;
        const float v1 = ok ? px[(2 * j + 1) * HW] : 0.0f;
        float r0, r1;
        hs[j * HP_STR + i] = pack_hi(v0, v1, r0, r1);
        ls[j * HP_STR + i] = pack_lo(r0, r1);
    }
}

__global__ void __launch_bounds__(256, 2)
batch_conv3x3_mma8_kernel(const float* __restrict__ x,
                          const float* __restrict__ w,
                          const float* __restrict__ bias,
                          float* __restrict__ out)
{
    extern __shared__ char smem[];
    float*    bias_s = reinterpret_cast<float*>(smem + SMEM_BIAS);
    uint32_t* whi    = reinterpret_cast<uint32_t*>(smem + SMEM_WHI);
    uint32_t* wlo    = reinterpret_cast<uint32_t*>(smem + SMEM_WLO);
    uint32_t* hp     = reinterpret_cast<uint32_t*>(smem + SMEM_HP);
    uint32_t* lp     = reinterpret_cast<uint32_t*>(smem + SMEM_LP);

    const int tid  = threadIdx.x;       // 0..255
    const int lane = tid & 31;
    const int wid  = tid >> 5;          // 0..7
    const int xh   = blockIdx.x;        // 0..1
    const int yg   = blockIdx.y;        // 0..31 (group of 8 rows)
    const int b    = blockIdx.z;        // 0..31
    const int x0   = xh * 128;
    const int y0   = yg * ROWS_PER_CTA;

    if (tid < CH) bias_s[tid] = bias[b * CH + tid];

    // ---- weights -> SMEM bf16 hi/lo: whi[oc*W_STR + tap*16 + pr]
    const float* wg = w + (size_t)b * (CH * CH * 9);
    for (int idx = tid; idx < CH * 9 * 16; idx += 256) {
        const int oc  = idx / 144;
        const int rem = idx - oc * 144;
        const int tap = rem >> 4;
        const int pr  = rem & 15;
        const float v0 = wg[(oc * CH + 2 * pr) * 9 + tap];
        const float v1 = wg[(oc * CH + 2 * pr + 1) * 9 + tap];
        float r0, r1;
        whi[oc * W_STR + rem] = pack_hi(v0, v1, r0, r1);
        wlo[oc * W_STR + rem] = pack_lo(r0, r1);
    }

    // ---- initial ring fill: input rows y0-1 .. y0+2
    const float* xb = x + (size_t)b * CH * HW;
    stage_row(hp, lp, xb, y0 - 1, x0, tid);
    stage_row(hp, lp, xb, y0,     x0, tid);
    stage_row(hp, lp, xb, y0 + 1, x0, tid);
    stage_row(hp, lp, xb, y0 + 2, x0, tid);
    __syncthreads();

    const int g  = lane >> 2;          // 0..7
    const int tg = lane & 3;           // 0..3
    const int p0 = (wid & 3) * 32;     // pixel base within 128
    const int rsel = wid >> 2;         // 0 or 1: which row of the pair

    float* ob_base = out + (size_t)b * CH * HW + x0;

#pragma unroll 1
    for (int s = 0; s < 4; ++s) {
        const int row = y0 + 2 * s + rsel;

        float acc[2][4][4];
#pragma unroll
        for (int nb = 0; nb < 4; ++nb) {
            const float b0v = bias_s[nb * 8 + tg * 2];
            const float b1v = bias_s[nb * 8 + tg * 2 + 1];
#pragma unroll
            for (int t = 0; t < 2; ++t) {
                acc[t][nb][0] = b0v; acc[t][nb][1] = b1v;
                acc[t][nb][2] = b0v; acc[t][nb][3] = b1v;
            }
        }

#pragma unroll
        for (int tap = 0; tap < 9; ++tap) {
            const int dy = tap / 3, dx = tap % 3;
            const int slot = (row - 1 + dy + 4) & 3;
            const uint32_t* hs = hp + slot * SLOT_W;
            const uint32_t* ls = lp + slot * SLOT_W;
#pragma unroll
            for (int half = 0; half < 2; ++half) {
                const int rj  = (half * 8 + tg) * HP_STR;
                const int rj4 = rj + 4 * HP_STR;
                uint32_t ah[2][4], al[2][4];
#pragma unroll
                for (int t = 0; t < 2; ++t) {
                    const int pb = p0 + t * 16 + g + dx;
                    ah[t][0] = hs[rj  + pb];  ah[t][1] = hs[rj  + pb + 8];
                    ah[t][2] = hs[rj4 + pb];  ah[t][3] = hs[rj4 + pb + 8];
                    al[t][0] = ls[rj  + pb];  al[t][1] = ls[rj  + pb + 8];
                    al[t][2] = ls[rj4 + pb];  al[t][3] = ls[rj4 + pb + 8];
                }
                const int wb = tap * 16 + half * 8 + tg;
#pragma unroll
                for (int nb = 0; nb < 4; ++nb) {
                    const int ocr = (nb * 8 + g) * W_STR + wb;
                    const uint32_t bh0 = whi[ocr], bh1 = whi[ocr + 4];
                    const uint32_t bl0 = wlo[ocr], bl1 = wlo[ocr + 4];
                    mma_bf16(acc[0][nb], ah[0], bh0, bh1);
                    mma_bf16(acc[1][nb], ah[1], bh0, bh1);
                    mma_bf16(acc[0][nb], al[0], bh0, bh1);
                    mma_bf16(acc[1][nb], al[1], bh0, bh1);
                    mma_bf16(acc[0][nb], ah[0], bl0, bl1);
                    mma_bf16(acc[1][nb], ah[1], bl0, bl1);
                }
            }
        }

        // ---- store this row's 32px x 32oc tile
        float* ob = ob_base + (size_t)row * WW;
#pragma unroll
        for (int t = 0; t < 2; ++t) {
            const int p = p0 + t * 16 + g;
#pragma unroll
            for (int nb = 0; nb < 4; ++nb) {
                const int oc0 = nb * 8 + tg * 2;
                ob[(size_t)oc0 * HW + p]           = acc[t][nb][0];
                ob[(size_t)(oc0 + 1) * HW + p]     = acc[t][nb][1];
                ob[(size_t)oc0 * HW + p + 8]       = acc[t][nb][2];
                ob[(size_t)(oc0 + 1) * HW + p + 8] = acc[t][nb][3];
            }
        }

        // ---- ring advance: all reads of oldest slots must be done first
        __syncthreads();
        if (s < 3) {
            stage_row(hp, lp, xb, y0 + 2 * s + 3, x0, tid);
            stage_row(hp, lp, xb, y0 + 2 * s + 4, x0, tid);
            __syncthreads();
        }
    }
}

extern "C" void kernel_launch(void* const* d_in, const int* in_sizes, int n_in,
                              void* d_out, int out_size)
{
    const float* x    = (const float*)d_in[0];
    const float* w    = (const float*)d_in[1];
    const float* bias = (const float*)d_in[2];
    float* out        = (float*)d_out;

    cudaFuncSetAttribute(batch_conv3x3_mma8_kernel,
                         cudaFuncAttributeMaxDynamicSharedMemorySize,
                         SMEM_TOTAL);

    dim3 grid(2, HH / ROWS_PER_CTA, BATCH);   // 2048 CTAs
    batch_conv3x3_mma8_kernel<<<grid, 256, SMEM_TOTAL>>>(x, w, bias, out);
}

// round 6
// speedup vs baseline: 2.1875x; 1.0086x over previous
#include <cuda_runtime.h>
#include <cuda_bf16.h>
#include <cstdint>

// ============================================================================
// BatchConv2D 3x3 via mma.sync bf16x3 (fp32 emulated), row-persistent CTAs.
// CTA = 256 threads (8 warps): one (batch, x-half of 128 px, 8 y rows), 32 oc.
// Per 2-row step: warps 0-3 -> row y, warps 4-7 -> row y+1; each warp does a
// 32px x 32oc tile. Input rows live in a 4-slot ring (hi/lo bf16 pair-packed);
// weights staged once per CTA.
// ============================================================================

#define BATCH 32
#define CH    32
#define HH    256
#define WW    256
#define HW    (HH * WW)
#define ROWS_PER_CTA 8

// Conflict-free SMEM strides (see bank proofs in R4):
//   input plane row stride 136 words: bank(136*tg + g) = 8tg+g, all distinct
//   weight oc stride 148 words:       bank(148*g + tg) = 20g+tg, all distinct
#define HP_STR  136                 // words per (slot,j) row, 130 used
#define W_STR   148                 // words per oc, 144 used
#define SLOT_W  (16 * HP_STR)       // 2176 words per ring slot (== 0 mod 32)

#define SMEM_BIAS 0                                   // 128 B
#define SMEM_WHI  128                                 // 18944 B
#define SMEM_WLO  (SMEM_WHI + CH * W_STR * 4)         // 19072
#define SMEM_HP   (SMEM_WLO + CH * W_STR * 4)         // 38016: 4 slots
#define SMEM_LP   (SMEM_HP + 4 * SLOT_W * 4)          // 72832
#define SMEM_TOTAL (SMEM_LP + 4 * SLOT_W * 4)         // 107648 B

__device__ __forceinline__ void mma_bf16(float* d, const uint32_t* a,
                                         uint32_t b0, uint32_t b1) {
    asm volatile(
        "mma.sync.aligned.m16n8k16.row.col.f32.bf16.bf16.f32 "
        "{%0,%1,%2,%3}, {%4,%5,%6,%7}, {%8,%9}, {%0,%1,%2,%3};\n"
        : "+f"(d[0]), "+f"(d[1]), "+f"(d[2]), "+f"(d[3])
        : "r"(a[0]), "r"(a[1]), "r"(a[2]), "r"(a[3]), "r"(b0), "r"(b1));
}

__device__ __forceinline__ uint32_t pack_hi(float v0, float v1,
                                            float& r0, float& r1) {
    __nv_bfloat16 h0 = __float2bfloat16(v0);
    __nv_bfloat16 h1 = __float2bfloat16(v1);
    r0 = v0 - __bfloat162float(h0);
    r1 = v1 - __bfloat162float(h1);
    return ((uint32_t)__bfloat16_as_ushort(h1) << 16) | __bfloat16_as_ushort(h0);
}

__device__ __forceinline__ uint32_t pack_lo(float r0, float r1) {
    __nv_bfloat16 l0 = __float2bfloat16(r0);
    __nv_bfloat16 l1 = __float2bfloat16(r1);
    return ((uint32_t)__bfloat16_as_ushort(l1) << 16) | __bfloat16_as_ushort(l0);
}

// Stage one global input row gy into ring slot (gy+4)&3. Zero-fills OOB.
__device__ __forceinline__ void stage_row(uint32_t* hp, uint32_t* lp,
                                          const float* __restrict__ xb,
                                          int gy, int x0, int tid) {
    const int slot = (gy + 4) & 3;
    uint32_t* hs = hp + slot * SLOT_W;
    uint32_t* ls = lp + slot * SLOT_W;
    const bool yok = (unsigned)gy < (unsigned)HH;
    const float* rowp = xb + (size_t)(yok ? gy : 0) * WW;
    for (int idx = tid; idx < 16 * 130; idx += 256) {
        const int j = idx / 130;
        const int i = idx - j * 130;
        const int gx = x0 - 1 + i;
        const bool ok = yok && ((unsigned)gx < (unsigned)WW);
        const float* px = rowp + (ok ? gx : 0);
        const float v0 = ok ? px[(2 * j) * HW] : 0.0f;
        const float v1 = ok ? px[(2 * j + 1) * HW] : 0.0f;
        float r0, r1;
        hs[j * HP_STR + i] = pack_hi(v0, v1, r0, r1);
        ls[j * HP_STR + i] = pack_lo(r0, r1);
    }
}

__global__ void __launch_bounds__(256, 2)
batch_conv3x3_mma8_kernel(const float* __restrict__ x,
                          const float* __restrict__ w,
                          const float* __restrict__ bias,
                          float* __restrict__ out)
{
    extern __shared__ char smem[];
    float*    bias_s = reinterpret_cast<float*>(smem + SMEM_BIAS);
    uint32_t* whi    = reinterpret_cast<uint32_t*>(smem + SMEM_WHI);
    uint32_t* wlo    = reinterpret_cast<uint32_t*>(smem + SMEM_WLO);
    uint32_t* hp     = reinterpret_cast<uint32_t*>(smem + SMEM_HP);
    uint32_t* lp     = reinterpret_cast<uint32_t*>(smem + SMEM_LP);

    const int tid  = threadIdx.x;       // 0..255
    const int lane = tid & 31;
    const int wid  = tid >> 5;          // 0..7
    const int xh   = blockIdx.x;        // 0..1
    const int yg   = blockIdx.y;        // 0..31 (group of 8 rows)
    const int b    = blockIdx.z;        // 0..31
    const int x0   = xh * 128;
    const int y0   = yg * ROWS_PER_CTA;

    if (tid < CH) bias_s[tid] = bias[b * CH + tid];

    // ---- weights -> SMEM bf16 hi/lo: whi[oc*W_STR + tap*16 + pr]
    const float* wg = w + (size_t)b * (CH * CH * 9);
    for (int idx = tid; idx < CH * 9 * 16; idx += 256) {
        const int oc  = idx / 144;
        const int rem = idx - oc * 144;
        const int tap = rem >> 4;
        const int pr  = rem & 15;
        const float v0 = wg[(oc * CH + 2 * pr) * 9 + tap];
        const float v1 = wg[(oc * CH + 2 * pr + 1) * 9 + tap];
        float r0, r1;
        whi[oc * W_STR + rem] = pack_hi(v0, v1, r0, r1);
        wlo[oc * W_STR + rem] = pack_lo(r0, r1);
    }

    // ---- initial ring fill: input rows y0-1 .. y0+2
    const float* xb = x + (size_t)b * CH * HW;
    stage_row(hp, lp, xb, y0 - 1, x0, tid);
    stage_row(hp, lp, xb, y0,     x0, tid);
    stage_row(hp, lp, xb, y0 + 1, x0, tid);
    stage_row(hp, lp, xb, y0 + 2, x0, tid);
    __syncthreads();

    const int g  = lane >> 2;          // 0..7
    const int tg = lane & 3;           // 0..3
    const int p0 = (wid & 3) * 32;     // pixel base within 128
    const int rsel = wid >> 2;         // 0 or 1: which row of the pair

    float* ob_base = out + (size_t)b * CH * HW + x0;

#pragma unroll 1
    for (int s = 0; s < 4; ++s) {
        const int row = y0 + 2 * s + rsel;

        float acc[2][4][4];
#pragma unroll
        for (int nb = 0; nb < 4; ++nb) {
            const float b0v = bias_s[nb * 8 + tg * 2];
            const float b1v = bias_s[nb * 8 + tg * 2 + 1];
#pragma unroll
            for (int t = 0; t < 2; ++t) {
                acc[t][nb][0] = b0v; acc[t][nb][1] = b1v;
                acc[t][nb][2] = b0v; acc[t][nb][3] = b1v;
            }
        }

#pragma unroll
        for (int tap = 0; tap < 9; ++tap) {
            const int dy = tap / 3, dx = tap % 3;
            const int slot = (row - 1 + dy + 4) & 3;
            const uint32_t* hs = hp + slot * SLOT_W;
            const uint32_t* ls = lp + slot * SLOT_W;
#pragma unroll
            for (int half = 0; half < 2; ++half) {
                const int rj  = (half * 8 + tg) * HP_STR;
                const int rj4 = rj + 4 * HP_STR;
                uint32_t ah[2][4], al[2][4];
#pragma unroll
                for (int t = 0; t < 2; ++t) {
                    const int pb = p0 + t * 16 + g + dx;
                    ah[t][0] = hs[rj  + pb];  ah[t][1] = hs[rj  + pb + 8];
                    ah[t][2] = hs[rj4 + pb];  ah[t][3] = hs[rj4 + pb + 8];
                    al[t][0] = ls[rj  + pb];  al[t][1] = ls[rj  + pb + 8];
                    al[t][2] = ls[rj4 + pb];  al[t][3] = ls[rj4 + pb + 8];
                }
                const int wb = tap * 16 + half * 8 + tg;
#pragma unroll
                for (int nb = 0; nb < 4; ++nb) {
                    const int ocr = (nb * 8 + g) * W_STR + wb;
                    const uint32_t bh0 = whi[ocr], bh1 = whi[ocr + 4];
                    const uint32_t bl0 = wlo[ocr], bl1 = wlo[ocr + 4];
                    mma_bf16(acc[0][nb], ah[0], bh0, bh1);
                    mma_bf16(acc[1][nb], ah[1], bh0, bh1);
                    mma_bf16(acc[0][nb], al[0], bh0, bh1);
                    mma_bf16(acc[1][nb], al[1], bh0, bh1);
                    mma_bf16(acc[0][nb], ah[0], bl0, bl1);
                    mma_bf16(acc[1][nb], ah[1], bl0, bl1);
                }
            }
        }

        // ---- store this row's 32px x 32oc tile
        float* ob = ob_base + (size_t)row * WW;
#pragma unroll
        for (int t = 0; t < 2; ++t) {
            const int p = p0 + t * 16 + g;
#pragma unroll
            for (int nb = 0; nb < 4; ++nb) {
                const int oc0 = nb * 8 + tg * 2;
                ob[(size_t)oc0 * HW + p]           = acc[t][nb][0];
                ob[(size_t)(oc0 + 1) * HW + p]     = acc[t][nb][1];
                ob[(size_t)oc0 * HW + p + 8]       = acc[t][nb][2];
                ob[(size_t)(oc0 + 1) * HW + p + 8] = acc[t][nb][3];
            }
        }

        // ---- ring advance: all reads of oldest slots must be done first
        __syncthreads();
        if (s < 3) {
            stage_row(hp, lp, xb, y0 + 2 * s + 3, x0, tid);
            stage_row(hp, lp, xb, y0 + 2 * s + 4, x0, tid);
            __syncthreads();
        }
    }
}

extern "C" void kernel_launch(void* const* d_in, const int* in_sizes, int n_in,
                              void* d_out, int out_size)
{
    const float* x    = (const float*)d_in[0];
    const float* w    = (const float*)d_in[1];
    const float* bias = (const float*)d_in[2];
    float* out        = (float*)d_out;

    cudaFuncSetAttribute(batch_conv3x3_mma8_kernel,
                         cudaFuncAttributeMaxDynamicSharedMemorySize,
                         SMEM_TOTAL);

    dim3 grid(2, HH / ROWS_PER_CTA, BATCH);   // 2048 CTAs
    batch_conv3x3_mma8_kernel<<<grid, 256, SMEM_TOTAL>>>(x, w, bias, out);
}